// round 16
// baseline (speedup 1.0000x reference)
#include <cuda_runtime.h>
#include <cuda_bf16.h>
#include <cuda_fp16.h>
#include <cstdint>
#include <math.h>

#define BB 8
#define NN 1024
#define DIMM 512
#define HH 8
#define DH 64
#define NTOK (BB*NN)          // 8192
#define INNER (HH*DH)         // 512

// Scratch (allocation-free rule: __device__ globals)
__device__ __half g_xh[(size_t)NTOK*DIMM];
__device__ __half g_xl[(size_t)NTOK*DIMM];
__device__ __half g_attf[(size_t)NTOK*INNER];
__device__ __half g_wqkvT_h[3*INNER*DIMM];
__device__ __half g_wqkvT_l[3*INNER*DIMM];
__device__ __half g_woutT_f[DIMM*INNER];
// q fp16 hi/lo split (pre-scaled by DH^-0.5*log2e); k,v single fp16
__device__ __half g_qh[BB*HH*NN*DH];
__device__ __half g_ql[BB*HH*NN*DH];
__device__ __half g_kf[BB*HH*NN*DH];
__device__ __half g_vf[BB*HH*NN*DH];

// ===================== helpers =====================
__device__ __forceinline__ uint32_t smem_to_u32(const void* p) {
    uint32_t a;
    asm("{ .reg .u64 t; cvta.to.shared.u64 t, %1; cvt.u32.u64 %0, t; }"
        : "=r"(a) : "l"(p));
    return a;
}
#define SW128(o) ((o) ^ (((o) >> 3) & 0x70))
#define SW64(o)  ((o) ^ (((o) >> 3) & 0x30))

__device__ __forceinline__ void ldmx4(uint32_t* r, uint32_t a) {
    asm volatile("ldmatrix.sync.aligned.m8n8.x4.shared.b16 {%0,%1,%2,%3}, [%4];"
        : "=r"(r[0]), "=r"(r[1]), "=r"(r[2]), "=r"(r[3]) : "r"(a));
}
__device__ __forceinline__ void ldmx4t(uint32_t* r, uint32_t a) {
    asm volatile("ldmatrix.sync.aligned.m8n8.x4.trans.shared.b16 {%0,%1,%2,%3}, [%4];"
        : "=r"(r[0]), "=r"(r[1]), "=r"(r[2]), "=r"(r[3]) : "r"(a));
}
__device__ __forceinline__ void mma16816h(float* d, const uint32_t* a, const uint32_t* b) {
    asm volatile("mma.sync.aligned.m16n8k16.row.col.f32.f16.f16.f32 "
        "{%0,%1,%2,%3}, {%4,%5,%6,%7}, {%8,%9}, {%0,%1,%2,%3};"
        : "+f"(d[0]), "+f"(d[1]), "+f"(d[2]), "+f"(d[3])
        : "r"(a[0]), "r"(a[1]), "r"(a[2]), "r"(a[3]), "r"(b[0]), "r"(b[1]));
}
__device__ __forceinline__ void cp16(uint32_t dst, const void* src) {
    asm volatile("cp.async.cg.shared.global [%0], [%1], 16;" :: "r"(dst), "l"(src));
}
#define CP_COMMIT() asm volatile("cp.async.commit_group;" ::: "memory")
#define CP_WAIT(n)  asm volatile("cp.async.wait_group %0;" :: "n"(n) : "memory")

__device__ __forceinline__ uint32_t pack_f16(float lo, float hi) {
    uint32_t r;
    asm("cvt.rn.f16x2.f32 %0, %1, %2;" : "=r"(r) : "f"(hi), "f"(lo));
    return r;
}
__device__ __forceinline__ uint32_t split_f16(float a, float b, uint32_t& lop) {
    uint32_t h = pack_f16(a, b);
    __half2 hh = *reinterpret_cast<__half2*>(&h);
    lop = pack_f16(a - __half2float(hh.x), b - __half2float(hh.y));
    return h;
}
__device__ __forceinline__ float ex2f(float x) {
    float r; asm("ex2.approx.f32 %0, %1;" : "=f"(r) : "f"(x)); return r;
}

// ===================== fused pre-pass =====================
// blocks [0, 4096): x fp32 -> xh/xl split (1024 floats per block)
// blocks [4096, 4864): transpose+split w_qkv (48 x 16 tiles of 32x32)
// blocks [4864, 5120): transpose w_out (16 x 16 tiles)
__global__ __launch_bounds__(256) void prepass_kernel(
    const float* __restrict__ x,
    const float* __restrict__ w_qkv,
    const float* __restrict__ w_out)
{
    __shared__ float ts[32][33];
    int blk = blockIdx.x;
    int t = threadIdx.x;
    if (blk < 4096) {
        int i = blk * 256 + t;
        float4 f = ((const float4*)x)[i];
        uint2 hv, lv;
        hv.x = split_f16(f.x, f.y, lv.x);
        hv.y = split_f16(f.z, f.w, lv.y);
        ((uint2*)g_xh)[i] = hv;
        ((uint2*)g_xl)[i] = lv;
        return;
    }
    int tx = t & 31, ty = t >> 5;   // 32 x 8
    if (blk < 4864) {
        int bi = blk - 4096;
        int n0 = (bi % 48) << 5, k0 = (bi / 48) << 5;
        const int N = 1536, K = 512;
        #pragma unroll
        for (int i = 0; i < 32; i += 8)
            ts[ty + i][tx] = w_qkv[(size_t)(k0 + ty + i) * N + n0 + tx];
        __syncthreads();
        #pragma unroll
        for (int i = 0; i < 32; i += 8) {
            float v = ts[tx][ty + i];
            __half h = __float2half(v);
            size_t o = (size_t)(n0 + ty + i) * K + k0 + tx;
            g_wqkvT_h[o] = h;
            g_wqkvT_l[o] = __float2half(v - __half2float(h));
        }
    } else {
        int bi = blk - 4864;
        int n0 = (bi % 16) << 5, k0 = (bi / 16) << 5;
        const int N = 512, K = 512;
        #pragma unroll
        for (int i = 0; i < 32; i += 8)
            ts[ty + i][tx] = w_out[(size_t)(k0 + ty + i) * N + n0 + tx];
        __syncthreads();
        #pragma unroll
        for (int i = 0; i < 32; i += 8)
            g_woutT_f[(size_t)(n0 + ty + i) * K + k0 + tx] = __float2half(ts[tx][ty + i]);
    }
}

// ===================== qkv GEMM =====================
// q tiles: 3-term (xh*Wh + xl*Wh + xh*Wl)  -> near-exact (q stored split)
// k tiles: 2-term (xh*Wh + xl*Wh)          -> W-rounding only
// v tiles: 1-term (xh*Wh)
__global__ __launch_bounds__(256, 2) void qkv_gemm_kernel(
    const float* __restrict__ bias,
    const float* __restrict__ rot, const float* __restrict__ tr)
{
    extern __shared__ char smem[];
    uint32_t base = (smem_to_u32(smem) + 127) & ~127u;
    int t = threadIdx.x, lane = t & 31, w = t >> 5;
    int m0 = blockIdx.y << 7, n0 = blockIdx.x << 7;
    int mbase = (w >> 2) * 64, nbase = (w & 3) * 32;
    const int which = blockIdx.x >> 2;          // 0=q, 1=k, 2=v
    const bool need_xl = (which < 2);           // q,k
    const bool need_wl = (which == 0);          // q only

    int rowc[2], k16c[2]; uint32_t swc[2];
    #pragma unroll
    for (int c = 0; c < 2; c++) {
        int ci = t + c * 256;
        rowc[c] = ci >> 2; k16c[c] = ci & 3;
        swc[c] = SW64((uint32_t)(rowc[c] * 64 + k16c[c] * 16));
    }

    float acc[4][4][4] = {};

    #define LOAD_ALL(kc, bb) do { \
        uint32_t bp = base + (bb) * 32768; \
        _Pragma("unroll") \
        for (int c = 0; c < 2; c++) { \
            size_t ga = (size_t)(m0 + rowc[c]) * 512 + (kc) * 32 + k16c[c] * 8; \
            size_t gb = (size_t)(n0 + rowc[c]) * 512 + (kc) * 32 + k16c[c] * 8; \
            cp16(bp +         swc[c], g_xh + ga); \
            cp16(bp + 16384 + swc[c], g_wqkvT_h + gb); \
            if (need_xl) cp16(bp +  8192 + swc[c], g_xl + ga); \
            if (need_wl) cp16(bp + 24576 + swc[c], g_wqkvT_l + gb); \
        } \
        CP_COMMIT(); \
    } while (0)

    int arow = lane & 15;
    int acolb = (lane >> 4) * 16;
    int bg = lane >> 3;
    int brow_in = lane & 7;

    LOAD_ALL(0, 0);
    CP_WAIT(0);
    __syncthreads();

    int buf = 0;
    for (int kc = 0; kc < 16; kc++) {
        if (kc < 15) LOAD_ALL(kc + 1, buf ^ 1);
        uint32_t AhS = base + buf * 32768;
        uint32_t AlS = AhS + 8192;
        uint32_t WhS = AhS + 16384;
        uint32_t WlS = AhS + 24576;
        #pragma unroll
        for (int ks = 0; ks < 2; ks++) {
            uint32_t ah[4][4], al[4][4], bf[4][2];
            #pragma unroll
            for (int i = 0; i < 4; i++) {
                uint32_t off = SW64((uint32_t)((mbase + i*16 + arow) * 64 + ks*32 + acolb));
                ldmx4(ah[i], AhS + off);
                if (need_xl) ldmx4(al[i], AlS + off);
            }
            #pragma unroll
            for (int jp = 0; jp < 2; jp++) {
                uint32_t off = SW64((uint32_t)((nbase + jp*16 + ((bg >> 1) << 3) + brow_in) * 64
                                               + ks*32 + ((bg & 1) << 4)));
                uint32_t r[4];
                ldmx4(r, WhS + off);
                bf[jp*2][0] = r[0]; bf[jp*2][1] = r[1];
                bf[jp*2+1][0] = r[2]; bf[jp*2+1][1] = r[3];
            }
            #pragma unroll
            for (int i = 0; i < 4; i++)
                #pragma unroll
                for (int j = 0; j < 4; j++) mma16816h(acc[i][j], ah[i], bf[j]);
            if (need_xl) {
                #pragma unroll
                for (int i = 0; i < 4; i++)
                    #pragma unroll
                    for (int j = 0; j < 4; j++) mma16816h(acc[i][j], al[i], bf[j]);
            }
            if (need_wl) {
                #pragma unroll
                for (int jp = 0; jp < 2; jp++) {
                    uint32_t off = SW64((uint32_t)((nbase + jp*16 + ((bg >> 1) << 3) + brow_in) * 64
                                                   + ks*32 + ((bg & 1) << 4)));
                    uint32_t r[4];
                    ldmx4(r, WlS + off);
                    bf[jp*2][0] = r[0]; bf[jp*2][1] = r[1];
                    bf[jp*2+1][0] = r[2]; bf[jp*2+1][1] = r[3];
                }
                #pragma unroll
                for (int i = 0; i < 4; i++)
                    #pragma unroll
                    for (int j = 0; j < 4; j++) mma16816h(acc[i][j], ah[i], bf[j]);
            }
        }
        if (kc < 15) CP_WAIT(0);
        __syncthreads();
        buf ^= 1;
    }

    const float QSCALE = 0.125f * 1.44269504088896f;   // DH^-0.5 * log2(e)
    bool evenlane = (lane & 1) == 0;
    #pragma unroll
    for (int i = 0; i < 4; i++) {
        int row_local = mbase + i*16 + (lane >> 2) + ((lane & 1) ? 8 : 0);
        int token = m0 + row_local;
        const float* R = rot + (size_t)token * 9;
        const float* T = tr + (size_t)token * 3;
        float R00=R[0],R01=R[1],R02=R[2],R10=R[3],R11=R[4],R12=R[5],R20=R[6],R21=R[7],R22=R[8];
        float T0=T[0],T1=T[1],T2=T[2];
        int b = token >> 10, n = token & (NN - 1);
        #pragma unroll
        for (int j = 0; j < 4; j++) {
            float x0 = __shfl_xor_sync(0xffffffffu, acc[i][j][0], 1);
            float x1 = __shfl_xor_sync(0xffffffffu, acc[i][j][1], 1);
            float x2 = __shfl_xor_sync(0xffffffffu, acc[i][j][2], 1);
            float x3 = __shfl_xor_sync(0xffffffffu, acc[i][j][3], 1);
            float v0, v1, v2, v3;
            if (evenlane) { v0 = acc[i][j][0]; v1 = acc[i][j][1]; v2 = x0; v3 = x1; }
            else          { v0 = x2; v1 = x3; v2 = acc[i][j][2]; v3 = acc[i][j][3]; }
            int cg = nbase + j*8 + ((lane >> 1) & 1) * 4;
            int cgl = n0 + cg;
            v0 += bias[cgl+0]; v1 += bias[cgl+1]; v2 += bias[cgl+2]; v3 += bias[cgl+3];
            int hh2 = (cgl & 511) >> 6;
            int d = cgl & 63;
            float y0 = R00*v0 + R01*v1 + R02*v2;
            float y1 = R10*v0 + R11*v1 + R12*v2;
            float y2 = R20*v0 + R21*v1 + R22*v2;
            float y3;
            if (which == 0) {
                y3 = v3 - (T0*y0 + T1*y1 + T2*y2);
                y0 *= QSCALE; y1 *= QSCALE; y2 *= QSCALE; y3 *= QSCALE;
            } else {
                y0 += T0 * v3; y1 += T1 * v3; y2 += T2 * v3;
                y3 = v3;
            }
            size_t o = ((size_t)(b * HH + hh2) * NN + n) * DH + d;
            if (which == 0) {
                uint2 hv, lv;
                hv.x = split_f16(y0, y1, lv.x);
                hv.y = split_f16(y2, y3, lv.y);
                *(uint2*)(g_qh + o) = hv;
                *(uint2*)(g_ql + o) = lv;
            } else {
                __half* dst = (which == 1) ? g_kf : g_vf;
                uint2 hv; hv.x = pack_f16(y0, y1); hv.y = pack_f16(y2, y3);
                *(uint2*)(dst + o) = hv;
            }
        }
    }
    #undef LOAD_ALL
}

// ===================== out projection (single x single, 1 MMA) =====================
__global__ __launch_bounds__(256, 2) void out_gemm_kernel(
    const float* __restrict__ bias, float* __restrict__ outp)
{
    extern __shared__ char smem[];
    uint32_t base = (smem_to_u32(smem) + 127) & ~127u;
    int t = threadIdx.x, lane = t & 31, w = t >> 5;
    int m0 = blockIdx.y << 7, n0 = blockIdx.x << 7;
    int mbase = (w >> 2) * 64, nbase = (w & 3) * 32;

    int rowc[2], k16c[2]; uint32_t swc[2];
    #pragma unroll
    for (int c = 0; c < 2; c++) {
        int ci = t + c * 256;
        rowc[c] = ci >> 2; k16c[c] = ci & 3;
        swc[c] = SW64((uint32_t)(rowc[c] * 64 + k16c[c] * 16));
    }

    float acc[4][4][4] = {};

    #define LOAD_O(kc, bb) do { \
        uint32_t bp = base + (bb) * 16384; \
        _Pragma("unroll") \
        for (int c = 0; c < 2; c++) { \
            size_t ga = (size_t)(m0 + rowc[c]) * 512 + (kc) * 32 + k16c[c] * 8; \
            size_t gb = (size_t)(n0 + rowc[c]) * 512 + (kc) * 32 + k16c[c] * 8; \
            cp16(bp +        swc[c], g_attf + ga); \
            cp16(bp + 8192 + swc[c], g_woutT_f + gb); \
        } \
        CP_COMMIT(); \
    } while (0)

    int arow = lane & 15;
    int acolb = (lane >> 4) * 16;
    int bg = lane >> 3;
    int brow_in = lane & 7;

    LOAD_O(0, 0);
    CP_WAIT(0);
    __syncthreads();

    int buf = 0;
    for (int kc = 0; kc < 16; kc++) {
        if (kc < 15) LOAD_O(kc + 1, buf ^ 1);
        uint32_t AfS = base + buf * 16384;
        uint32_t BfS = AfS + 8192;
        #pragma unroll
        for (int ks = 0; ks < 2; ks++) {
            uint32_t af[4][4], bf[4][2];
            #pragma unroll
            for (int i = 0; i < 4; i++) {
                uint32_t off = SW64((uint32_t)((mbase + i*16 + arow) * 64 + ks*32 + acolb));
                ldmx4(af[i], AfS + off);
            }
            #pragma unroll
            for (int jp = 0; jp < 2; jp++) {
                uint32_t off = SW64((uint32_t)((nbase + jp*16 + ((bg >> 1) << 3) + brow_in) * 64
                                               + ks*32 + ((bg & 1) << 4)));
                uint32_t r[4];
                ldmx4(r, BfS + off);
                bf[jp*2][0] = r[0]; bf[jp*2][1] = r[1];
                bf[jp*2+1][0] = r[2]; bf[jp*2+1][1] = r[3];
            }
            #pragma unroll
            for (int i = 0; i < 4; i++)
                #pragma unroll
                for (int j = 0; j < 4; j++) mma16816h(acc[i][j], af[i], bf[j]);
        }
        if (kc < 15) CP_WAIT(0);
        __syncthreads();
        buf ^= 1;
    }

    bool evenlane = (lane & 1) == 0;
    #pragma unroll
    for (int i = 0; i < 4; i++) {
        int row_local = mbase + i*16 + (lane >> 2) + ((lane & 1) ? 8 : 0);
        int token = m0 + row_local;
        #pragma unroll
        for (int j = 0; j < 4; j++) {
            float x0 = __shfl_xor_sync(0xffffffffu, acc[i][j][0], 1);
            float x1 = __shfl_xor_sync(0xffffffffu, acc[i][j][1], 1);
            float x2 = __shfl_xor_sync(0xffffffffu, acc[i][j][2], 1);
            float x3 = __shfl_xor_sync(0xffffffffu, acc[i][j][3], 1);
            float v0, v1, v2, v3;
            if (evenlane) { v0 = acc[i][j][0]; v1 = acc[i][j][1]; v2 = x0; v3 = x1; }
            else          { v0 = x2; v1 = x3; v2 = acc[i][j][2]; v3 = acc[i][j][3]; }
            int cgl = n0 + nbase + j*8 + ((lane >> 1) & 1) * 4;
            float4 ov;
            ov.x = v0 + bias[cgl+0]; ov.y = v1 + bias[cgl+1];
            ov.z = v2 + bias[cgl+2]; ov.w = v3 + bias[cgl+3];
            *(float4*)(outp + (size_t)token * 512 + cgl) = ov;
        }
    }
    #undef LOAD_O
}

// ===================== mma.sync flash attention =====================
// QK: 2-term (qh*k + ql*k), k single fp16, qh register-resident;
// PV: 1-term (p single x v single).
// Key chunks 64, double-buffered; smem buf 16KB: KF 8K | VF 8K.
#define ABUF 16384
#define AQH 32768
#define AQL 49152

__global__ __launch_bounds__(256, 2) void attn_kernel(
    const float* __restrict__ rot, const float* __restrict__ tr)
{
    extern __shared__ char smem[];
    uint32_t base = (smem_to_u32(smem) + 127) & ~127u;
    int t = threadIdx.x, lane = t & 31, w = t >> 5;
    int bh = blockIdx.y;
    int q0 = blockIdx.x << 7;
    int wm = w << 4;

    int rkv[2], kkv[2]; uint32_t swkv[2];
    #pragma unroll
    for (int c = 0; c < 2; c++) {
        int ci = t + c * 256;
        rkv[c] = ci >> 3; kkv[c] = ci & 7;
        swkv[c] = SW128((uint32_t)(rkv[c] * 128 + kkv[c] * 16));
    }
    int rq[4], kq[4]; uint32_t swq[4];
    #pragma unroll
    for (int c = 0; c < 4; c++) {
        int ci = t + c * 256;
        rq[c] = ci >> 3; kq[c] = ci & 7;
        swq[c] = SW128((uint32_t)(rq[c] * 128 + kq[c] * 16));
    }
    const size_t bhbase = (size_t)bh * NN * DH;

    #define LOAD_KV(cc, bb) do { \
        uint32_t bp = base + (bb) * ABUF; \
        _Pragma("unroll") \
        for (int c = 0; c < 2; c++) { \
            size_t go = bhbase + ((size_t)((cc) * 64 + rkv[c])) * 64 + kkv[c] * 8; \
            cp16(bp +        swkv[c], g_kf + go); \
            cp16(bp + 8192 + swkv[c], g_vf + go); \
        } \
        CP_COMMIT(); \
    } while (0)

    {
        #pragma unroll
        for (int c = 0; c < 4; c++) {
            size_t go = bhbase + ((size_t)(q0 + rq[c])) * 64 + kq[c] * 8;
            cp16(base + AQH + swq[c], g_qh + go);
            cp16(base + AQL + swq[c], g_ql + go);
        }
        CP_COMMIT();
    }
    LOAD_KV(0, 0);
    CP_WAIT(1);
    __syncthreads();

    // Q-hi fragments register-resident for all 16 chunks (ql reloaded per chunk)
    uint32_t qhr[4][4];
    #pragma unroll
    for (int ks = 0; ks < 4; ks++) {
        uint32_t qoff = SW128((uint32_t)((wm + (lane & 15)) * 128
                                         + ks*32 + (lane >> 4) * 16));
        ldmx4(qhr[ks], base + AQH + qoff);
    }

    int bg = lane >> 3, brow_in = lane & 7;

    float acc[8][4] = {};
    float m1 = -1e30f, m2 = -1e30f, l1 = 0.f, l2 = 0.f;

    int buf = 0;
    for (int kc = 0; kc < 16; kc++) {
        if (kc < 15) LOAD_KV(kc + 1, buf ^ 1);
        CP_WAIT(1);
        if (kc == 15) CP_WAIT(0);
        __syncthreads();
        uint32_t KFs = base + buf * ABUF;
        uint32_t VFs = KFs + 8192;

        // ---- scores (log2 domain): 16 q x 64 keys, 2-term fp16 ----
        float s[8][4] = {};
        #pragma unroll
        for (int ks = 0; ks < 4; ks++) {
            uint32_t qoff = SW128((uint32_t)((wm + (lane & 15)) * 128
                                             + ks*32 + (lane >> 4) * 16));
            uint32_t ql[4];
            ldmx4(ql, base + AQL + qoff);
            uint32_t kf[8][2];
            #pragma unroll
            for (int jp = 0; jp < 4; jp++) {
                uint32_t off = SW128((uint32_t)((jp*16 + ((bg >> 1) << 3) + brow_in) * 128
                                                + ks*32 + ((bg & 1) << 4)));
                uint32_t r[4];
                ldmx4(r, KFs + off);
                kf[2*jp][0] = r[0]; kf[2*jp][1] = r[1];
                kf[2*jp+1][0] = r[2]; kf[2*jp+1][1] = r[3];
            }
            #pragma unroll
            for (int n8 = 0; n8 < 8; n8++) mma16816h(s[n8], qhr[ks], kf[n8]);
            #pragma unroll
            for (int n8 = 0; n8 < 8; n8++) mma16816h(s[n8], ql, kf[n8]);
        }

        // ---- max reduce ----
        float mloc1 = -1e30f, mloc2 = -1e30f;
        #pragma unroll
        for (int nt = 0; nt < 8; nt++) {
            mloc1 = fmaxf(mloc1, fmaxf(s[nt][0], s[nt][1]));
            mloc2 = fmaxf(mloc2, fmaxf(s[nt][2], s[nt][3]));
        }
        mloc1 = fmaxf(mloc1, __shfl_xor_sync(0xffffffffu, mloc1, 1));
        mloc1 = fmaxf(mloc1, __shfl_xor_sync(0xffffffffu, mloc1, 2));
        mloc2 = fmaxf(mloc2, __shfl_xor_sync(0xffffffffu, mloc2, 1));
        mloc2 = fmaxf(mloc2, __shfl_xor_sync(0xffffffffu, mloc2, 2));
        float m1n = fmaxf(m1, mloc1), m2n = fmaxf(m2, mloc2);
        float a1 = ex2f(m1 - m1n), a2 = ex2f(m2 - m2n);
        m1 = m1n; m2 = m2n;

        #pragma unroll
        for (int nt = 0; nt < 8; nt++) {
            acc[nt][0] *= a1; acc[nt][1] *= a1;
            acc[nt][2] *= a2; acc[nt][3] *= a2;
        }

        // ---- fused exp + PV (p single fp16, v single fp16) ----
        float ps1 = 0.f, ps2 = 0.f;
        #pragma unroll
        for (int kx = 0; kx < 4; kx++) {
            float p00 = ex2f(s[2*kx][0]   - m1n);
            float p01 = ex2f(s[2*kx][1]   - m1n);
            float p02 = ex2f(s[2*kx][2]   - m2n);
            float p03 = ex2f(s[2*kx][3]   - m2n);
            float p10 = ex2f(s[2*kx+1][0] - m1n);
            float p11 = ex2f(s[2*kx+1][1] - m1n);
            float p12 = ex2f(s[2*kx+1][2] - m2n);
            float p13 = ex2f(s[2*kx+1][3] - m2n);
            ps1 += p00 + p01 + p10 + p11;
            ps2 += p02 + p03 + p12 + p13;
            uint32_t ph[4];
            ph[0] = pack_f16(p00, p01);
            ph[1] = pack_f16(p02, p03);
            ph[2] = pack_f16(p10, p11);
            ph[3] = pack_f16(p12, p13);
            uint32_t vf[8][2];
            #pragma unroll
            for (int np = 0; np < 4; np++) {
                uint32_t off = SW128((uint32_t)((kx*16 + (lane & 15)) * 128
                                                + np*32 + (lane >> 4) * 16));
                uint32_t rv[4];
                ldmx4t(rv, VFs + off);
                vf[2*np][0] = rv[0]; vf[2*np][1] = rv[1];
                vf[2*np+1][0] = rv[2]; vf[2*np+1][1] = rv[3];
            }
            #pragma unroll
            for (int n8 = 0; n8 < 8; n8++) mma16816h(acc[n8], ph, vf[n8]);
        }
        ps1 += __shfl_xor_sync(0xffffffffu, ps1, 1);
        ps1 += __shfl_xor_sync(0xffffffffu, ps1, 2);
        ps2 += __shfl_xor_sync(0xffffffffu, ps2, 1);
        ps2 += __shfl_xor_sync(0xffffffffu, ps2, 2);
        l1 = l1 * a1 + ps1;
        l2 = l2 * a2 + ps2;

        __syncthreads();
        buf ^= 1;
    }

    // ---- epilogue: normalize + inverse pose + relayout -> single fp16 ----
    float inv1 = 1.f / l1, inv2 = 1.f / l2;
    bool odd = lane & 1;
    float inv = odd ? inv2 : inv1;
    int r = (lane >> 2) + (odd ? 8 : 0);
    int nq = q0 + wm + r;
    int b = bh >> 3, h = bh & 7;
    int token = b * NN + nq;
    const float* R = rot + (size_t)token * 9;
    const float* T = tr + (size_t)token * 3;
    float R00=R[0],R01=R[1],R02=R[2],R10=R[3],R11=R[4],R12=R[5],R20=R[6],R21=R[7],R22=R[8];
    float T0=T[0],T1=T[1],T2=T[2];
    int grp = (lane >> 1) & 1;
    #pragma unroll
    for (int nt = 0; nt < 8; nt++) {
        float o0 = acc[nt][0], o1 = acc[nt][1], o2 = acc[nt][2], o3 = acc[nt][3];
        float x0 = __shfl_xor_sync(0xffffffffu, o0, 1);
        float x1 = __shfl_xor_sync(0xffffffffu, o1, 1);
        float x2 = __shfl_xor_sync(0xffffffffu, o2, 1);
        float x3 = __shfl_xor_sync(0xffffffffu, o3, 1);
        float v0, v1, v2, v3;
        if (!odd) { v0 = o0; v1 = o1; v2 = x0; v3 = x1; }
        else      { v0 = x2; v1 = x3; v2 = o2; v3 = o3; }
        v0 *= inv; v1 *= inv; v2 *= inv; v3 *= inv;
        float u0 = v0 - T0*v3, u1 = v1 - T1*v3, u2 = v2 - T2*v3;
        float y0 = R00*u0 + R10*u1 + R20*u2;
        float y1 = R01*u0 + R11*u1 + R21*u2;
        float y2 = R02*u0 + R12*u1 + R22*u2;
        size_t o = (size_t)token * INNER + h * DH + nt * 8 + grp * 4;
        uint2 hv;
        hv.x = pack_f16(y0, y1);
        hv.y = pack_f16(y2, v3);
        *(uint2*)(g_attf + o) = hv;
    }
    #undef LOAD_KV
}

// ---------------------------------------------------------------------------
extern "C" void kernel_launch(void* const* d_in, const int* in_sizes, int n_in,
                              void* d_out, int out_size)
{
    const float* x     = (const float*)d_in[0];
    const float* rot   = (const float*)d_in[1];
    const float* tr    = (const float*)d_in[2];
    const float* w_qkv = (const float*)d_in[3];
    const float* b_qkv = (const float*)d_in[4];
    const float* w_out = (const float*)d_in[5];
    const float* b_out = (const float*)d_in[6];
    float* out = (float*)d_out;

    // fused pre-pass: x split (4096 blocks) + w_qkv (768) + w_out (256)
    prepass_kernel<<<5120, 256>>>(x, w_qkv, w_out);

    int qkv_smem = 2 * 32768 + 128;
    cudaFuncSetAttribute(qkv_gemm_kernel, cudaFuncAttributeMaxDynamicSharedMemorySize, qkv_smem);
    qkv_gemm_kernel<<<dim3(12, 64), 256, qkv_smem>>>(b_qkv, rot, tr);

    int attn_smem = 2 * ABUF + 32768 + 128;   // 64KB + pad
    cudaFuncSetAttribute(attn_kernel, cudaFuncAttributeMaxDynamicSharedMemorySize, attn_smem);
    attn_kernel<<<dim3(8, 64), 256, attn_smem>>>(rot, tr);

    int out_smem = 2 * 16384 + 128;
    cudaFuncSetAttribute(out_gemm_kernel, cudaFuncAttributeMaxDynamicSharedMemorySize, out_smem);
    out_gemm_kernel<<<dim3(4, 64), 256, out_smem>>>(b_out, out);
}

// round 17
// speedup vs baseline: 1.0087x; 1.0087x over previous
#include <cuda_runtime.h>
#include <cuda_bf16.h>
#include <cuda_fp16.h>
#include <cstdint>
#include <math.h>

#define BB 8
#define NN 1024
#define DIMM 512
#define HH 8
#define DH 64
#define NTOK (BB*NN)          // 8192
#define INNER (HH*DH)         // 512

// Scratch (allocation-free rule: __device__ globals)
__device__ __half g_xh[(size_t)NTOK*DIMM];
__device__ __half g_xl[(size_t)NTOK*DIMM];
__device__ __half g_attf[(size_t)NTOK*INNER];
__device__ __half g_wqkvT_h[3*INNER*DIMM];
__device__ __half g_wqkvT_l[3*INNER*DIMM];
__device__ __half g_woutT_f[DIMM*INNER];
// q fp16 hi/lo split (pre-scaled by DH^-0.5*log2e); k,v single fp16
__device__ __half g_qh[BB*HH*NN*DH];
__device__ __half g_ql[BB*HH*NN*DH];
__device__ __half g_kf[BB*HH*NN*DH];
__device__ __half g_vf[BB*HH*NN*DH];

// ===================== helpers =====================
__device__ __forceinline__ uint32_t smem_to_u32(const void* p) {
    uint32_t a;
    asm("{ .reg .u64 t; cvta.to.shared.u64 t, %1; cvt.u32.u64 %0, t; }"
        : "=r"(a) : "l"(p));
    return a;
}
#define SW128(o) ((o) ^ (((o) >> 3) & 0x70))
#define SW64(o)  ((o) ^ (((o) >> 3) & 0x30))

__device__ __forceinline__ void ldmx4(uint32_t* r, uint32_t a) {
    asm volatile("ldmatrix.sync.aligned.m8n8.x4.shared.b16 {%0,%1,%2,%3}, [%4];"
        : "=r"(r[0]), "=r"(r[1]), "=r"(r[2]), "=r"(r[3]) : "r"(a));
}
__device__ __forceinline__ void ldmx4t(uint32_t* r, uint32_t a) {
    asm volatile("ldmatrix.sync.aligned.m8n8.x4.trans.shared.b16 {%0,%1,%2,%3}, [%4];"
        : "=r"(r[0]), "=r"(r[1]), "=r"(r[2]), "=r"(r[3]) : "r"(a));
}
__device__ __forceinline__ void mma16816h(float* d, const uint32_t* a, const uint32_t* b) {
    asm volatile("mma.sync.aligned.m16n8k16.row.col.f32.f16.f16.f32 "
        "{%0,%1,%2,%3}, {%4,%5,%6,%7}, {%8,%9}, {%0,%1,%2,%3};"
        : "+f"(d[0]), "+f"(d[1]), "+f"(d[2]), "+f"(d[3])
        : "r"(a[0]), "r"(a[1]), "r"(a[2]), "r"(a[3]), "r"(b[0]), "r"(b[1]));
}
__device__ __forceinline__ void cp16(uint32_t dst, const void* src) {
    asm volatile("cp.async.cg.shared.global [%0], [%1], 16;" :: "r"(dst), "l"(src));
}
#define CP_COMMIT() asm volatile("cp.async.commit_group;" ::: "memory")
#define CP_WAIT(n)  asm volatile("cp.async.wait_group %0;" :: "n"(n) : "memory")

__device__ __forceinline__ uint32_t pack_f16(float lo, float hi) {
    uint32_t r;
    asm("cvt.rn.f16x2.f32 %0, %1, %2;" : "=r"(r) : "f"(hi), "f"(lo));
    return r;
}
__device__ __forceinline__ uint32_t split_f16(float a, float b, uint32_t& lop) {
    uint32_t h = pack_f16(a, b);
    __half2 hh = *reinterpret_cast<__half2*>(&h);
    lop = pack_f16(a - __half2float(hh.x), b - __half2float(hh.y));
    return h;
}
__device__ __forceinline__ float ex2f(float x) {
    float r; asm("ex2.approx.f32 %0, %1;" : "=f"(r) : "f"(x)); return r;
}

// ===================== fused pre-pass =====================
// blocks [0, 4096): x fp32 -> xh/xl split (1024 floats per block)
// blocks [4096, 4864): transpose+split w_qkv (48 x 16 tiles of 32x32)
// blocks [4864, 5120): transpose w_out (16 x 16 tiles)
__global__ __launch_bounds__(256) void prepass_kernel(
    const float* __restrict__ x,
    const float* __restrict__ w_qkv,
    const float* __restrict__ w_out)
{
    __shared__ float ts[32][33];
    int blk = blockIdx.x;
    int t = threadIdx.x;
    if (blk < 4096) {
        int i = blk * 256 + t;
        float4 f = ((const float4*)x)[i];
        uint2 hv, lv;
        hv.x = split_f16(f.x, f.y, lv.x);
        hv.y = split_f16(f.z, f.w, lv.y);
        ((uint2*)g_xh)[i] = hv;
        ((uint2*)g_xl)[i] = lv;
        return;
    }
    int tx = t & 31, ty = t >> 5;   // 32 x 8
    if (blk < 4864) {
        int bi = blk - 4096;
        int n0 = (bi % 48) << 5, k0 = (bi / 48) << 5;
        const int N = 1536, K = 512;
        #pragma unroll
        for (int i = 0; i < 32; i += 8)
            ts[ty + i][tx] = w_qkv[(size_t)(k0 + ty + i) * N + n0 + tx];
        __syncthreads();
        #pragma unroll
        for (int i = 0; i < 32; i += 8) {
            float v = ts[tx][ty + i];
            __half h = __float2half(v);
            size_t o = (size_t)(n0 + ty + i) * K + k0 + tx;
            g_wqkvT_h[o] = h;
            g_wqkvT_l[o] = __float2half(v - __half2float(h));
        }
    } else {
        int bi = blk - 4864;
        int n0 = (bi % 16) << 5, k0 = (bi / 16) << 5;
        const int N = 512, K = 512;
        #pragma unroll
        for (int i = 0; i < 32; i += 8)
            ts[ty + i][tx] = w_out[(size_t)(k0 + ty + i) * N + n0 + tx];
        __syncthreads();
        #pragma unroll
        for (int i = 0; i < 32; i += 8)
            g_woutT_f[(size_t)(n0 + ty + i) * K + k0 + tx] = __float2half(ts[tx][ty + i]);
    }
}

// ===================== qkv GEMM =====================
// q tiles: 3-term (xh*Wh + xl*Wh + xh*Wl)  -> near-exact (q stored split)
// k tiles: 2-term (xh*Wh + xl*Wh)          -> W-rounding only
// v tiles: 1-term (xh*Wh)
__global__ __launch_bounds__(256, 2) void qkv_gemm_kernel(
    const float* __restrict__ bias,
    const float* __restrict__ rot, const float* __restrict__ tr)
{
    extern __shared__ char smem[];
    uint32_t base = (smem_to_u32(smem) + 127) & ~127u;
    int t = threadIdx.x, lane = t & 31, w = t >> 5;
    int m0 = blockIdx.y << 7, n0 = blockIdx.x << 7;
    int mbase = (w >> 2) * 64, nbase = (w & 3) * 32;
    const int which = blockIdx.x >> 2;          // 0=q, 1=k, 2=v
    const bool need_xl = (which < 2);           // q,k
    const bool need_wl = (which == 0);          // q only

    int rowc[2], k16c[2]; uint32_t swc[2];
    #pragma unroll
    for (int c = 0; c < 2; c++) {
        int ci = t + c * 256;
        rowc[c] = ci >> 2; k16c[c] = ci & 3;
        swc[c] = SW64((uint32_t)(rowc[c] * 64 + k16c[c] * 16));
    }

    float acc[4][4][4] = {};

    #define LOAD_ALL(kc, bb) do { \
        uint32_t bp = base + (bb) * 32768; \
        _Pragma("unroll") \
        for (int c = 0; c < 2; c++) { \
            size_t ga = (size_t)(m0 + rowc[c]) * 512 + (kc) * 32 + k16c[c] * 8; \
            size_t gb = (size_t)(n0 + rowc[c]) * 512 + (kc) * 32 + k16c[c] * 8; \
            cp16(bp +         swc[c], g_xh + ga); \
            cp16(bp + 16384 + swc[c], g_wqkvT_h + gb); \
            if (need_xl) cp16(bp +  8192 + swc[c], g_xl + ga); \
            if (need_wl) cp16(bp + 24576 + swc[c], g_wqkvT_l + gb); \
        } \
        CP_COMMIT(); \
    } while (0)

    int arow = lane & 15;
    int acolb = (lane >> 4) * 16;
    int bg = lane >> 3;
    int brow_in = lane & 7;

    LOAD_ALL(0, 0);
    CP_WAIT(0);
    __syncthreads();

    int buf = 0;
    for (int kc = 0; kc < 16; kc++) {
        if (kc < 15) LOAD_ALL(kc + 1, buf ^ 1);
        uint32_t AhS = base + buf * 32768;
        uint32_t AlS = AhS + 8192;
        uint32_t WhS = AhS + 16384;
        uint32_t WlS = AhS + 24576;
        #pragma unroll
        for (int ks = 0; ks < 2; ks++) {
            uint32_t ah[4][4], al[4][4], bf[4][2];
            #pragma unroll
            for (int i = 0; i < 4; i++) {
                uint32_t off = SW64((uint32_t)((mbase + i*16 + arow) * 64 + ks*32 + acolb));
                ldmx4(ah[i], AhS + off);
                if (need_xl) ldmx4(al[i], AlS + off);
            }
            #pragma unroll
            for (int jp = 0; jp < 2; jp++) {
                uint32_t off = SW64((uint32_t)((nbase + jp*16 + ((bg >> 1) << 3) + brow_in) * 64
                                               + ks*32 + ((bg & 1) << 4)));
                uint32_t r[4];
                ldmx4(r, WhS + off);
                bf[jp*2][0] = r[0]; bf[jp*2][1] = r[1];
                bf[jp*2+1][0] = r[2]; bf[jp*2+1][1] = r[3];
            }
            #pragma unroll
            for (int i = 0; i < 4; i++)
                #pragma unroll
                for (int j = 0; j < 4; j++) mma16816h(acc[i][j], ah[i], bf[j]);
            if (need_xl) {
                #pragma unroll
                for (int i = 0; i < 4; i++)
                    #pragma unroll
                    for (int j = 0; j < 4; j++) mma16816h(acc[i][j], al[i], bf[j]);
            }
            if (need_wl) {
                #pragma unroll
                for (int jp = 0; jp < 2; jp++) {
                    uint32_t off = SW64((uint32_t)((nbase + jp*16 + ((bg >> 1) << 3) + brow_in) * 64
                                                   + ks*32 + ((bg & 1) << 4)));
                    uint32_t r[4];
                    ldmx4(r, WlS + off);
                    bf[jp*2][0] = r[0]; bf[jp*2][1] = r[1];
                    bf[jp*2+1][0] = r[2]; bf[jp*2+1][1] = r[3];
                }
                #pragma unroll
                for (int i = 0; i < 4; i++)
                    #pragma unroll
                    for (int j = 0; j < 4; j++) mma16816h(acc[i][j], ah[i], bf[j]);
            }
        }
        if (kc < 15) CP_WAIT(0);
        __syncthreads();
        buf ^= 1;
    }

    const float QSCALE = 0.125f * 1.44269504088896f;   // DH^-0.5 * log2(e)
    bool evenlane = (lane & 1) == 0;
    #pragma unroll
    for (int i = 0; i < 4; i++) {
        int row_local = mbase + i*16 + (lane >> 2) + ((lane & 1) ? 8 : 0);
        int token = m0 + row_local;
        const float* R = rot + (size_t)token * 9;
        const float* T = tr + (size_t)token * 3;
        float R00=R[0],R01=R[1],R02=R[2],R10=R[3],R11=R[4],R12=R[5],R20=R[6],R21=R[7],R22=R[8];
        float T0=T[0],T1=T[1],T2=T[2];
        int b = token >> 10, n = token & (NN - 1);
        #pragma unroll
        for (int j = 0; j < 4; j++) {
            float x0 = __shfl_xor_sync(0xffffffffu, acc[i][j][0], 1);
            float x1 = __shfl_xor_sync(0xffffffffu, acc[i][j][1], 1);
            float x2 = __shfl_xor_sync(0xffffffffu, acc[i][j][2], 1);
            float x3 = __shfl_xor_sync(0xffffffffu, acc[i][j][3], 1);
            float v0, v1, v2, v3;
            if (evenlane) { v0 = acc[i][j][0]; v1 = acc[i][j][1]; v2 = x0; v3 = x1; }
            else          { v0 = x2; v1 = x3; v2 = acc[i][j][2]; v3 = acc[i][j][3]; }
            int cg = nbase + j*8 + ((lane >> 1) & 1) * 4;
            int cgl = n0 + cg;
            v0 += bias[cgl+0]; v1 += bias[cgl+1]; v2 += bias[cgl+2]; v3 += bias[cgl+3];
            int hh2 = (cgl & 511) >> 6;
            int d = cgl & 63;
            float y0 = R00*v0 + R01*v1 + R02*v2;
            float y1 = R10*v0 + R11*v1 + R12*v2;
            float y2 = R20*v0 + R21*v1 + R22*v2;
            float y3;
            if (which == 0) {
                y3 = v3 - (T0*y0 + T1*y1 + T2*y2);
                y0 *= QSCALE; y1 *= QSCALE; y2 *= QSCALE; y3 *= QSCALE;
            } else {
                y0 += T0 * v3; y1 += T1 * v3; y2 += T2 * v3;
                y3 = v3;
            }
            size_t o = ((size_t)(b * HH + hh2) * NN + n) * DH + d;
            if (which == 0) {
                uint2 hv, lv;
                hv.x = split_f16(y0, y1, lv.x);
                hv.y = split_f16(y2, y3, lv.y);
                *(uint2*)(g_qh + o) = hv;
                *(uint2*)(g_ql + o) = lv;
            } else {
                __half* dst = (which == 1) ? g_kf : g_vf;
                uint2 hv; hv.x = pack_f16(y0, y1); hv.y = pack_f16(y2, y3);
                *(uint2*)(dst + o) = hv;
            }
        }
    }
    #undef LOAD_ALL
}

// ===================== out projection (single x single, 1 MMA) =====================
// K-chunk 64 (SW128 rows), 8 iterations; buffers 2 x 32KB -> 2 CTAs/SM.
__global__ __launch_bounds__(256, 2) void out_gemm_kernel(
    const float* __restrict__ bias, float* __restrict__ outp)
{
    extern __shared__ char smem[];
    uint32_t base = (smem_to_u32(smem) + 127) & ~127u;
    int t = threadIdx.x, lane = t & 31, w = t >> 5;
    int m0 = blockIdx.y << 7, n0 = blockIdx.x << 7;
    int mbase = (w >> 2) * 64, nbase = (w & 3) * 32;

    // loader: per 16KB tile, 1024 x 16B chunks; 4 per thread per tile
    int rowc[4], k16c[4]; uint32_t swc[4];
    #pragma unroll
    for (int c = 0; c < 4; c++) {
        int ci = t + c * 256;
        rowc[c] = ci >> 3; k16c[c] = ci & 7;
        swc[c] = SW128((uint32_t)(rowc[c] * 128 + k16c[c] * 16));
    }

    float acc[4][4][4] = {};

    #define LOAD_O(kc, bb) do { \
        uint32_t bp = base + (bb) * 32768; \
        _Pragma("unroll") \
        for (int c = 0; c < 4; c++) { \
            size_t ga = (size_t)(m0 + rowc[c]) * 512 + (kc) * 64 + k16c[c] * 8; \
            size_t gb = (size_t)(n0 + rowc[c]) * 512 + (kc) * 64 + k16c[c] * 8; \
            cp16(bp +         swc[c], g_attf + ga); \
            cp16(bp + 16384 + swc[c], g_woutT_f + gb); \
        } \
        CP_COMMIT(); \
    } while (0)

    int arow = lane & 15;
    int acolb = (lane >> 4) * 16;
    int bg = lane >> 3;
    int brow_in = lane & 7;

    LOAD_O(0, 0);
    CP_WAIT(0);
    __syncthreads();

    int buf = 0;
    for (int kc = 0; kc < 8; kc++) {
        if (kc < 7) LOAD_O(kc + 1, buf ^ 1);
        uint32_t AfS = base + buf * 32768;
        uint32_t BfS = AfS + 16384;
        #pragma unroll
        for (int ks = 0; ks < 4; ks++) {
            uint32_t af[4][4], bf[4][2];
            #pragma unroll
            for (int i = 0; i < 4; i++) {
                uint32_t off = SW128((uint32_t)((mbase + i*16 + arow) * 128 + ks*32 + acolb));
                ldmx4(af[i], AfS + off);
            }
            #pragma unroll
            for (int jp = 0; jp < 2; jp++) {
                uint32_t off = SW128((uint32_t)((nbase + jp*16 + ((bg >> 1) << 3) + brow_in) * 128
                                                + ks*32 + ((bg & 1) << 4)));
                uint32_t r[4];
                ldmx4(r, BfS + off);
                bf[jp*2][0] = r[0]; bf[jp*2][1] = r[1];
                bf[jp*2+1][0] = r[2]; bf[jp*2+1][1] = r[3];
            }
            #pragma unroll
            for (int i = 0; i < 4; i++)
                #pragma unroll
                for (int j = 0; j < 4; j++) mma16816h(acc[i][j], af[i], bf[j]);
        }
        if (kc < 7) CP_WAIT(0);
        __syncthreads();
        buf ^= 1;
    }

    bool evenlane = (lane & 1) == 0;
    #pragma unroll
    for (int i = 0; i < 4; i++) {
        int row_local = mbase + i*16 + (lane >> 2) + ((lane & 1) ? 8 : 0);
        int token = m0 + row_local;
        #pragma unroll
        for (int j = 0; j < 4; j++) {
            float x0 = __shfl_xor_sync(0xffffffffu, acc[i][j][0], 1);
            float x1 = __shfl_xor_sync(0xffffffffu, acc[i][j][1], 1);
            float x2 = __shfl_xor_sync(0xffffffffu, acc[i][j][2], 1);
            float x3 = __shfl_xor_sync(0xffffffffu, acc[i][j][3], 1);
            float v0, v1, v2, v3;
            if (evenlane) { v0 = acc[i][j][0]; v1 = acc[i][j][1]; v2 = x0; v3 = x1; }
            else          { v0 = x2; v1 = x3; v2 = acc[i][j][2]; v3 = acc[i][j][3]; }
            int cgl = n0 + nbase + j*8 + ((lane >> 1) & 1) * 4;
            float4 ov;
            ov.x = v0 + bias[cgl+0]; ov.y = v1 + bias[cgl+1];
            ov.z = v2 + bias[cgl+2]; ov.w = v3 + bias[cgl+3];
            *(float4*)(outp + (size_t)token * 512 + cgl) = ov;
        }
    }
    #undef LOAD_O
}

// ===================== mma.sync flash attention =====================
// QK: 2-term (qh*k + ql*k), k single fp16; PV: 1-term (p single x v single).
// Key chunks 64, double-buffered; smem buf 16KB: KF 8K | VF 8K.
#define ABUF 16384
#define AQH 32768
#define AQL 49152

__global__ __launch_bounds__(256, 2) void attn_kernel(
    const float* __restrict__ rot, const float* __restrict__ tr)
{
    extern __shared__ char smem[];
    uint32_t base = (smem_to_u32(smem) + 127) & ~127u;
    int t = threadIdx.x, lane = t & 31, w = t >> 5;
    int bh = blockIdx.y;
    int q0 = blockIdx.x << 7;
    int wm = w << 4;

    int rkv[2], kkv[2]; uint32_t swkv[2];
    #pragma unroll
    for (int c = 0; c < 2; c++) {
        int ci = t + c * 256;
        rkv[c] = ci >> 3; kkv[c] = ci & 7;
        swkv[c] = SW128((uint32_t)(rkv[c] * 128 + kkv[c] * 16));
    }
    int rq[4], kq[4]; uint32_t swq[4];
    #pragma unroll
    for (int c = 0; c < 4; c++) {
        int ci = t + c * 256;
        rq[c] = ci >> 3; kq[c] = ci & 7;
        swq[c] = SW128((uint32_t)(rq[c] * 128 + kq[c] * 16));
    }
    const size_t bhbase = (size_t)bh * NN * DH;

    #define LOAD_KV(cc, bb) do { \
        uint32_t bp = base + (bb) * ABUF; \
        _Pragma("unroll") \
        for (int c = 0; c < 2; c++) { \
            size_t go = bhbase + ((size_t)((cc) * 64 + rkv[c])) * 64 + kkv[c] * 8; \
            cp16(bp +        swkv[c], g_kf + go); \
            cp16(bp + 8192 + swkv[c], g_vf + go); \
        } \
        CP_COMMIT(); \
    } while (0)

    {
        #pragma unroll
        for (int c = 0; c < 4; c++) {
            size_t go = bhbase + ((size_t)(q0 + rq[c])) * 64 + kq[c] * 8;
            cp16(base + AQH + swq[c], g_qh + go);
            cp16(base + AQL + swq[c], g_ql + go);
        }
        CP_COMMIT();
    }
    LOAD_KV(0, 0);
    CP_WAIT(1);
    __syncthreads();

    int bg = lane >> 3, brow_in = lane & 7;

    float acc[8][4] = {};
    float m1 = -1e30f, m2 = -1e30f, l1 = 0.f, l2 = 0.f;

    int buf = 0;
    for (int kc = 0; kc < 16; kc++) {
        if (kc < 15) LOAD_KV(kc + 1, buf ^ 1);
        CP_WAIT(1);
        if (kc == 15) CP_WAIT(0);
        __syncthreads();
        uint32_t KFs = base + buf * ABUF;
        uint32_t VFs = KFs + 8192;

        // ---- scores (log2 domain): 16 q x 64 keys, 2-term fp16 ----
        float s[8][4] = {};
        #pragma unroll
        for (int ks = 0; ks < 4; ks++) {
            uint32_t qoff = SW128((uint32_t)((wm + (lane & 15)) * 128
                                             + ks*32 + (lane >> 4) * 16));
            uint32_t qh[4], ql[4];
            ldmx4(qh, base + AQH + qoff);
            ldmx4(ql, base + AQL + qoff);
            uint32_t kf[8][2];
            #pragma unroll
            for (int jp = 0; jp < 4; jp++) {
                uint32_t off = SW128((uint32_t)((jp*16 + ((bg >> 1) << 3) + brow_in) * 128
                                                + ks*32 + ((bg & 1) << 4)));
                uint32_t r[4];
                ldmx4(r, KFs + off);
                kf[2*jp][0] = r[0]; kf[2*jp][1] = r[1];
                kf[2*jp+1][0] = r[2]; kf[2*jp+1][1] = r[3];
            }
            #pragma unroll
            for (int n8 = 0; n8 < 8; n8++) mma16816h(s[n8], qh, kf[n8]);
            #pragma unroll
            for (int n8 = 0; n8 < 8; n8++) mma16816h(s[n8], ql, kf[n8]);
        }

        // ---- max reduce ----
        float mloc1 = -1e30f, mloc2 = -1e30f;
        #pragma unroll
        for (int nt = 0; nt < 8; nt++) {
            mloc1 = fmaxf(mloc1, fmaxf(s[nt][0], s[nt][1]));
            mloc2 = fmaxf(mloc2, fmaxf(s[nt][2], s[nt][3]));
        }
        mloc1 = fmaxf(mloc1, __shfl_xor_sync(0xffffffffu, mloc1, 1));
        mloc1 = fmaxf(mloc1, __shfl_xor_sync(0xffffffffu, mloc1, 2));
        mloc2 = fmaxf(mloc2, __shfl_xor_sync(0xffffffffu, mloc2, 1));
        mloc2 = fmaxf(mloc2, __shfl_xor_sync(0xffffffffu, mloc2, 2));
        float m1n = fmaxf(m1, mloc1), m2n = fmaxf(m2, mloc2);
        float a1 = ex2f(m1 - m1n), a2 = ex2f(m2 - m2n);
        m1 = m1n; m2 = m2n;

        #pragma unroll
        for (int nt = 0; nt < 8; nt++) {
            acc[nt][0] *= a1; acc[nt][1] *= a1;
            acc[nt][2] *= a2; acc[nt][3] *= a2;
        }

        // ---- fused exp + PV (p single fp16, v single fp16) ----
        float ps1 = 0.f, ps2 = 0.f;
        #pragma unroll
        for (int kx = 0; kx < 4; kx++) {
            float p00 = ex2f(s[2*kx][0]   - m1n);
            float p01 = ex2f(s[2*kx][1]   - m1n);
            float p02 = ex2f(s[2*kx][2]   - m2n);
            float p03 = ex2f(s[2*kx][3]   - m2n);
            float p10 = ex2f(s[2*kx+1][0] - m1n);
            float p11 = ex2f(s[2*kx+1][1] - m1n);
            float p12 = ex2f(s[2*kx+1][2] - m2n);
            float p13 = ex2f(s[2*kx+1][3] - m2n);
            ps1 += p00 + p01 + p10 + p11;
            ps2 += p02 + p03 + p12 + p13;
            uint32_t ph[4];
            ph[0] = pack_f16(p00, p01);
            ph[1] = pack_f16(p02, p03);
            ph[2] = pack_f16(p10, p11);
            ph[3] = pack_f16(p12, p13);
            uint32_t vf[8][2];
            #pragma unroll
            for (int np = 0; np < 4; np++) {
                uint32_t off = SW128((uint32_t)((kx*16 + (lane & 15)) * 128
                                                + np*32 + (lane >> 4) * 16));
                uint32_t rv[4];
                ldmx4t(rv, VFs + off);
                vf[2*np][0] = rv[0]; vf[2*np][1] = rv[1];
                vf[2*np+1][0] = rv[2]; vf[2*np+1][1] = rv[3];
            }
            #pragma unroll
            for (int n8 = 0; n8 < 8; n8++) mma16816h(acc[n8], ph, vf[n8]);
        }
        ps1 += __shfl_xor_sync(0xffffffffu, ps1, 1);
        ps1 += __shfl_xor_sync(0xffffffffu, ps1, 2);
        ps2 += __shfl_xor_sync(0xffffffffu, ps2, 1);
        ps2 += __shfl_xor_sync(0xffffffffu, ps2, 2);
        l1 = l1 * a1 + ps1;
        l2 = l2 * a2 + ps2;

        __syncthreads();
        buf ^= 1;
    }

    // ---- epilogue: normalize + inverse pose + relayout -> single fp16 ----
    float inv1 = 1.f / l1, inv2 = 1.f / l2;
    bool odd = lane & 1;
    float inv = odd ? inv2 : inv1;
    int r = (lane >> 2) + (odd ? 8 : 0);
    int nq = q0 + wm + r;
    int b = bh >> 3, h = bh & 7;
    int token = b * NN + nq;
    const float* R = rot + (size_t)token * 9;
    const float* T = tr + (size_t)token * 3;
    float R00=R[0],R01=R[1],R02=R[2],R10=R[3],R11=R[4],R12=R[5],R20=R[6],R21=R[7],R22=R[8];
    float T0=T[0],T1=T[1],T2=T[2];
    int grp = (lane >> 1) & 1;
    #pragma unroll
    for (int nt = 0; nt < 8; nt++) {
        float o0 = acc[nt][0], o1 = acc[nt][1], o2 = acc[nt][2], o3 = acc[nt][3];
        float x0 = __shfl_xor_sync(0xffffffffu, o0, 1);
        float x1 = __shfl_xor_sync(0xffffffffu, o1, 1);
        float x2 = __shfl_xor_sync(0xffffffffu, o2, 1);
        float x3 = __shfl_xor_sync(0xffffffffu, o3, 1);
        float v0, v1, v2, v3;
        if (!odd) { v0 = o0; v1 = o1; v2 = x0; v3 = x1; }
        else      { v0 = x2; v1 = x3; v2 = o2; v3 = o3; }
        v0 *= inv; v1 *= inv; v2 *= inv; v3 *= inv;
        float u0 = v0 - T0*v3, u1 = v1 - T1*v3, u2 = v2 - T2*v3;
        float y0 = R00*u0 + R10*u1 + R20*u2;
        float y1 = R01*u0 + R11*u1 + R21*u2;
        float y2 = R02*u0 + R12*u1 + R22*u2;
        size_t o = (size_t)token * INNER + h * DH + nt * 8 + grp * 4;
        uint2 hv;
        hv.x = pack_f16(y0, y1);
        hv.y = pack_f16(y2, v3);
        *(uint2*)(g_attf + o) = hv;
    }
    #undef LOAD_KV
}

// ---------------------------------------------------------------------------
extern "C" void kernel_launch(void* const* d_in, const int* in_sizes, int n_in,
                              void* d_out, int out_size)
{
    const float* x     = (const float*)d_in[0];
    const float* rot   = (const float*)d_in[1];
    const float* tr    = (const float*)d_in[2];
    const float* w_qkv = (const float*)d_in[3];
    const float* b_qkv = (const float*)d_in[4];
    const float* w_out = (const float*)d_in[5];
    const float* b_out = (const float*)d_in[6];
    float* out = (float*)d_out;

    // fused pre-pass: x split (4096 blocks) + w_qkv (768) + w_out (256)
    prepass_kernel<<<5120, 256>>>(x, w_qkv, w_out);

    int qkv_smem = 2 * 32768 + 128;
    cudaFuncSetAttribute(qkv_gemm_kernel, cudaFuncAttributeMaxDynamicSharedMemorySize, qkv_smem);
    qkv_gemm_kernel<<<dim3(12, 64), 256, qkv_smem>>>(b_qkv, rot, tr);

    int attn_smem = 2 * ABUF + 32768 + 128;   // 64KB + pad
    cudaFuncSetAttribute(attn_kernel, cudaFuncAttributeMaxDynamicSharedMemorySize, attn_smem);
    attn_kernel<<<dim3(8, 64), 256, attn_smem>>>(rot, tr);

    int out_smem = 2 * 32768 + 128;   // K-chunk 64: 2 x 32KB
    cudaFuncSetAttribute(out_gemm_kernel, cudaFuncAttributeMaxDynamicSharedMemorySize, out_smem);
    out_gemm_kernel<<<dim3(4, 64), 256, out_smem>>>(b_out, out);
}